// round 16
// baseline (speedup 1.0000x reference)
#include <cuda_runtime.h>

#define NG      8000
#define NGATE   16000
#define NCTA    125
#define GPC     128
#define NGP     64       // gate-pairs per CTA
#define NB      32
#define NHB     16       // half-batch
#define NP      64
#define NITER   50
#define NT      256
#define DTF     0.02f
#define INV_DT_SKIP 2.5f

#define FS2     144      // F row stride (16B-aligned, odd-16 for bank spread)

typedef unsigned long long u64;

// ---------------- device scratch ----------------
__device__ float    g_SA[4][NP*NHB];      // rotating buffers, half A: S[p][b0..15]
__device__ float    g_SB[4][NP*NHB];      // half B
__device__ u64      g_invdup[2][NP*NP];   // inverses, j-major, value-duplicated
__device__ unsigned g_ctr[2][32];         // [0][0]=A counter, [1][0]=B counter (separate lines)

// ---------------- helpers ----------------
__device__ __forceinline__ u64 fma2(u64 a, u64 b, u64 c) {
    u64 d; asm("fma.rn.f32x2 %0, %1, %2, %3;" : "=l"(d) : "l"(a), "l"(b), "l"(c)); return d;
}
__device__ __forceinline__ u64 mul2(u64 a, u64 b) {
    u64 d; asm("mul.rn.f32x2 %0, %1, %2;" : "=l"(d) : "l"(a), "l"(b)); return d;
}
__device__ __forceinline__ u64 dup2(float x) {
    unsigned xi = __float_as_uint(x);
    u64 d; asm("mov.b64 %0, {%1, %2};" : "=l"(d) : "r"(xi), "r"(xi)); return d;
}
__device__ __forceinline__ void unpack2(u64 v, float& lo, float& hi) {
    unsigned a, b; asm("mov.b64 {%0, %1}, %2;" : "=r"(a), "=r"(b) : "l"(v));
    lo = __uint_as_float(a); hi = __uint_as_float(b);
}
__device__ __forceinline__ unsigned ldacq(const unsigned* p) {
    unsigned v; asm volatile("ld.acquire.gpu.u32 %0, [%1];" : "=r"(v) : "l"(p)); return v;
}
__device__ __forceinline__ unsigned atom_inc_acqrel(unsigned* p) {
    unsigned v, one = 1u;
    asm volatile("atom.add.acq_rel.gpu.u32 %0, [%1], %2;" : "=r"(v) : "l"(p), "r"(one)); return v;
}
__device__ __forceinline__ void redadd(float* p, float v) {
    asm volatile("red.add.f32 [%0], %1;" :: "l"(p), "f"(v));
}

// ---------------- init: matrix inverses (dup'd) + reset ----------------
__global__ void init_kernel(const float* __restrict__ Ap) {
    __shared__ float M[NP][2*NP + 1];
    __shared__ float fac[NP];
    __shared__ float s_piv;
    int t = threadIdx.x;

    for (int pass = 0; pass < 2; ++pass) {
        float dscale = (pass == 0) ? 1.0f : 3.0f;
        float ascale = (pass == 0) ? DTF : 2.0f * DTF;
        for (int idx = t; idx < NP*NP; idx += 256) {
            int i = idx >> 6, j = idx & 63;
            M[i][j]      = ((i == j) ? dscale : 0.0f) - ascale * Ap[idx];
            M[i][j + NP] = (i == j) ? 1.0f : 0.0f;
        }
        __syncthreads();
        for (int c = 0; c < NP; ++c) {
            if (t == 0) s_piv = 1.0f / M[c][c];
            __syncthreads();
            float ip = s_piv;
            if (t < 2*NP) M[c][t] *= ip;
            if (t < NP)   fac[t] = (t == c) ? 0.0f : M[t][c];
            __syncthreads();
            for (int idx = t; idx < NP * 2 * NP; idx += 256) {
                int r = idx >> 7, j = idx & 127;
                if (r != c) M[r][j] -= fac[r] * M[c][j];
            }
            __syncthreads();
        }
        for (int idx = t; idx < NP*NP; idx += 256) {
            int j = idx >> 6, i = idx & 63;
            g_invdup[pass][idx] = dup2(M[i][j + NP]);   // [j][i] dup'd
        }
        __syncthreads();
    }
    for (int idx = t; idx < 4*NP*NHB; idx += 256) {
        ((float*)g_SA)[idx] = 0.0f;
        ((float*)g_SB)[idx] = 0.0f;
    }
    if (t == 0) { g_ctr[0][0] = 0u; g_ctr[1][0] = 0u; }
    __threadfence();
}

// ---------------- SMEM layout (bytes) ----------------
#define SM_W2    0                 // [k 64][gp 64][c 4 as 2x u64, swizzled] : 131072
#define SM_P2    131072            // [gp 64][p 64] u64 gate-paired          : 32768
#define SM_F     163840            // [gp 64] stride 144: [b 16] u64         : 9216
#define SM_AD    173056            // [k 64][b 32] u64, value-dup'd          : 16384
#define SM_R     189440            // [j 64] stride 136: [bp 8] u64          : 8704
#define SMEM_TOTAL 198144

extern __shared__ char smem_raw[];

__global__ void __launch_bounds__(NT, 1)
persist_kernel(const float* __restrict__ state,
               const float* __restrict__ Wu, const float* __restrict__ Wv,
               const float* __restrict__ Pp, float* __restrict__ out)
{
    const int t   = threadIdx.x;
    const int cta = blockIdx.x;

    // ================= one-time staging =================
    // W2: [k][gp][c], c01 block at +sw, c23 block at +(sw^16), sw = (gp&4)*4
    for (int idx = t; idx < GPC*4*16; idx += NT) {
        int g = idx >> 6, c = (idx >> 4) & 3, k4 = idx & 15;
        int gate = cta * GPC + g;
        const float4* src = (const float4*)((gate < NG) ? Wu : Wv);
        int base = (gate < NG) ? gate : (gate - NG);
        float4 v = __ldg(src + (base + c*NG)*16 + k4);
        float vv[4] = {v.x, v.y, v.z, v.w};
        int gp = g >> 1, ge = g & 1;
        int sw = (gp & 4) * 4;
        int base16 = (c >> 1) ? (sw ^ 16) : sw;
        int off = gp*32 + base16 + (c & 1)*8 + ge*4;
        #pragma unroll
        for (int j = 0; j < 4; ++j) {
            int k = k4*4 + j;
            *(float*)(smem_raw + SM_W2 + k*2048 + off) = vv[j];
        }
    }
    // P2: [gp][p] u64 = (Pp[p][g0], Pp[p][g1])
    for (int idx = t; idx < NGP*NP; idx += NT) {
        int gp = idx & 63, p = idx >> 6;
        float2 v = __ldg((const float2*)(Pp + p*NGATE + cta*GPC + gp*2));
        *(float2*)(smem_raw + SM_P2 + gp*512 + p*8) = v;
    }
    // a_dup from state: [k][b] u64 dup'd
    for (int idx = t; idx < NB*NP; idx += NT) {
        int b = idx >> 6, k = idx & 63;
        *(u64*)(smem_raw + SM_AD + k*256 + b*8) = dup2(state[idx]);
    }

    // ---- static mappings ----
    // phase 1: thread = (gate-pair gp1 64, batch-quad bq 4) : 4 batches/thread/half
    const int gp1 = t >> 2, bq = t & 3;
    const int swp = (gp1 & 4) * 4;
    const int wAoff = gp1*32 + swp;
    const int wBoff = gp1*32 + (swp ^ 16);
    // phase 2: thread = (batch b2 16, p-quad p4 16)
    const int b2 = t & 15, p4 = t >> 4;
    // matvec: thread = (b-pair bpu 8, i-pair ipr 32)
    const int bpu = t & 7, ipr = t >> 3;

    float aprv[2][4], fprv[2][4];
    #pragma unroll
    for (int h = 0; h < 2; ++h)
        #pragma unroll
        for (int e = 0; e < 4; ++e) { aprv[h][e] = 0.0f; fprv[h][e] = 0.0f; }

    __syncthreads();

    for (int it = 0; it < NITER; ++it) {
        // ============ compute + arrive, halves A then B ============
        #pragma unroll
        for (int h = 0; h < 2; ++h) {
            // ---- phase 1 (half h): z = a@W^T gate-paired, 4c x 4b ----
            {
                u64 acc[4][4];
                #pragma unroll
                for (int c = 0; c < 4; ++c)
                    #pragma unroll
                    for (int i = 0; i < 4; ++i) acc[c][i] = 0;

                const char* aKb = smem_raw + SM_AD + h*128 + bq*32;
                ulonglong2 w01 = *(const ulonglong2*)(smem_raw + SM_W2 + wAoff);
                ulonglong2 w23 = *(const ulonglong2*)(smem_raw + SM_W2 + wBoff);
                ulonglong2 a0 = *(const ulonglong2*)(aKb);
                ulonglong2 a1 = *(const ulonglong2*)(aKb + 16);

                #pragma unroll 1
                for (int k = 0; k < NP; ++k) {
                    ulonglong2 nw01, nw23, n0, n1;
                    if (k < NP - 1) {
                        const char* row = smem_raw + SM_W2 + (k + 1)*2048;
                        nw01 = *(const ulonglong2*)(row + wAoff);
                        nw23 = *(const ulonglong2*)(row + wBoff);
                        n0 = *(const ulonglong2*)(aKb + (k + 1)*256);
                        n1 = *(const ulonglong2*)(aKb + (k + 1)*256 + 16);
                    }
                    u64 av[4] = {a0.x, a0.y, a1.x, a1.y};
                    #pragma unroll
                    for (int i = 0; i < 4; ++i) {
                        acc[0][i] = fma2(w01.x, av[i], acc[0][i]);
                        acc[1][i] = fma2(w01.y, av[i], acc[1][i]);
                        acc[2][i] = fma2(w23.x, av[i], acc[2][i]);
                        acc[3][i] = fma2(w23.y, av[i], acc[3][i]);
                    }
                    if (k < NP - 1) { w01 = nw01; w23 = nw23; a0 = n0; a1 = n1; }
                }
                // f = u*dx + v*dy (gate-paired per batch), store [gp][b16]
                char* fb = smem_raw + SM_F + gp1*FS2 + bq*32;
                u64 f0 = fma2(acc[1][0], acc[3][0], mul2(acc[0][0], acc[2][0]));
                u64 f1 = fma2(acc[1][1], acc[3][1], mul2(acc[0][1], acc[2][1]));
                u64 f2 = fma2(acc[1][2], acc[3][2], mul2(acc[0][2], acc[2][2]));
                u64 f3 = fma2(acc[1][3], acc[3][3], mul2(acc[0][3], acc[2][3]));
                *(ulonglong2*)(fb)      = make_ulonglong2(f0, f1);
                *(ulonglong2*)(fb + 16) = make_ulonglong2(f2, f3);
            }
            __syncthreads();

            // ---- phase 2 (half h): S[p][b] += sum_gp f[gp][b] .* P2[gp][p] ----
            {
                u64 q0 = 0, q1 = 0, q2 = 0, q3 = 0;
                const char* fb2 = smem_raw + SM_F + b2*8;
                const char* pb  = smem_raw + SM_P2 + p4*32;
                #pragma unroll 4
                for (int gp = 0; gp < NGP; ++gp) {
                    u64 fv = *(const u64*)(fb2 + gp*FS2);
                    ulonglong2 P0 = *(const ulonglong2*)(pb + gp*512);
                    ulonglong2 P1 = *(const ulonglong2*)(pb + gp*512 + 16);
                    q0 = fma2(fv, P0.x, q0);
                    q1 = fma2(fv, P0.y, q1);
                    q2 = fma2(fv, P1.x, q2);
                    q3 = fma2(fv, P1.y, q3);
                }
                float* Sb = (h ? g_SB : g_SA)[it & 3];
                float lo, hi;
                unpack2(q0, lo, hi); redadd(Sb + (p4*4    )*NHB + b2, lo + hi);
                unpack2(q1, lo, hi); redadd(Sb + (p4*4 + 1)*NHB + b2, lo + hi);
                unpack2(q2, lo, hi); redadd(Sb + (p4*4 + 2)*NHB + b2, lo + hi);
                unpack2(q3, lo, hi); redadd(Sb + (p4*4 + 3)*NHB + b2, lo + hi);
            }
            __threadfence();
            __syncthreads();
            if (t == 0) atom_inc_acqrel(&g_ctr[h][0]);
            // no extra sync: next half's phase-1 F writes are ordered by the sync above
        }

        if (it == NITER - 1 && cta != 0) return;   // arrived at both; CTA0 finishes

        // ============ wait + update, halves A then B ============
        #pragma unroll
        for (int h = 0; h < 2; ++h) {
            if (t == 0) {
                const unsigned tgt = (unsigned)NCTA * (unsigned)(it + 1);
                while (ldacq(&g_ctr[h][0]) < tgt) { }
            }
            __syncthreads();

            const float* Sb = (h ? g_SB : g_SA)[it & 3];
            // zero this half's buffer from 1 iter ago (reused at it+3; ordered by barrier chain)
            if (t < 9) {
                int z = cta*9 + t;
                if (z < NP*NHB) __stcg(&(h ? g_SB : g_SA)[(it + 3) & 3][z], 0.0f);
            }

            // ---- step 1: r ----
            #pragma unroll
            for (int e = 0; e < 4; ++e) {
                int idx = t + e*NT;              // 0..1023 = j*16 + bl
                int bl = idx & 15, j = idx >> 4;
                float f  = -__ldcv(Sb + idx);
                float av = *(const float*)(smem_raw + SM_AD + j*256 + (h*16 + bl)*8);
                float r;
                if (it == 0) r = av + DTF * f;
                else         r = 4.0f*av - aprv[h][e] + 4.0f*DTF*f - 2.0f*DTF*fprv[h][e];
                aprv[h][e] = av; fprv[h][e] = f;
                *(float*)(smem_raw + SM_R + j*136 + (bl >> 1)*8 + (bl & 1)*4) = r;
            }
            __syncthreads();

            // ---- step 2: a_next = inv @ r; write dup'd a directly ----
            {
                const u64* invd = g_invdup[(it == 0) ? 0 : 1] + ipr*2;
                u64 m0 = 0, m1 = 0;
                const char* rb = smem_raw + SM_R + bpu*8;
                #pragma unroll 4
                for (int j = 0; j < NP; ++j) {
                    u64 rv = *(const u64*)(rb + j*136);
                    ulonglong2 iv = __ldg((const ulonglong2*)(invd + j*64));
                    m0 = fma2(rv, iv.x, m0);
                    m1 = fma2(rv, iv.y, m1);
                }
                int i0 = ipr*2;
                int b0 = h*16 + 2*bpu;
                float l0, h0v, l1, h1v;
                unpack2(m0, l0, h0v); unpack2(m1, l1, h1v);
                if (it < NITER - 1) {
                    *(u64*)(smem_raw + SM_AD + (i0    )*256 + (b0    )*8) = dup2(l0);
                    *(u64*)(smem_raw + SM_AD + (i0    )*256 + (b0 + 1)*8) = dup2(h0v);
                    *(u64*)(smem_raw + SM_AD + (i0 + 1)*256 + (b0    )*8) = dup2(l1);
                    *(u64*)(smem_raw + SM_AD + (i0 + 1)*256 + (b0 + 1)*8) = dup2(h1v);
                } else {   // only CTA0 reaches here
                    out[(b0    )*NP + i0    ] = (l0  - __ldg(&state[(b0    )*NP + i0    ])) * INV_DT_SKIP;
                    out[(b0 + 1)*NP + i0    ] = (h0v - __ldg(&state[(b0 + 1)*NP + i0    ])) * INV_DT_SKIP;
                    out[(b0    )*NP + i0 + 1] = (l1  - __ldg(&state[(b0    )*NP + i0 + 1])) * INV_DT_SKIP;
                    out[(b0 + 1)*NP + i0 + 1] = (h1v - __ldg(&state[(b0 + 1)*NP + i0 + 1])) * INV_DT_SKIP;
                }
            }
            __syncthreads();
        }
    }
}

// ---------------- launcher ----------------
extern "C" void kernel_launch(void* const* d_in, const int* in_sizes, int n_in,
                              void* d_out, int out_size) {
    const float* state = (const float*)d_in[0];
    const float* Ap    = (const float*)d_in[1];
    const float* Wu    = (const float*)d_in[2];
    const float* Wv    = (const float*)d_in[3];
    const float* Pp    = (const float*)d_in[4];
    float* out = (float*)d_out;
    (void)in_sizes; (void)n_in; (void)out_size;

    cudaFuncSetAttribute(persist_kernel,
                         cudaFuncAttributeMaxDynamicSharedMemorySize, SMEM_TOTAL);

    init_kernel<<<1, 256>>>(Ap);
    persist_kernel<<<NCTA, NT, SMEM_TOTAL>>>(state, Wu, Wv, Pp, out);
}

// round 17
// speedup vs baseline: 1.2825x; 1.2825x over previous
#include <cuda_runtime.h>

#define NG      8000
#define NGATE   16000
#define NCTA    296
#define GPC     55       // max gates per CTA (2000/37 slicing)
#define NB      32
#define NP      64
#define NITER   50
#define NT      256
#define DTF     0.02f
#define INV_DT_SKIP 2.5f

typedef unsigned long long u64;

// ---------------- device scratch ----------------
__device__ float    g_S[4][NB*NP];        // rotating reduction buffers [b][p]
__device__ float    g_invT[2][NP*NP];     // inverses, j-major: [j*64+i] = inv[i][j]
__device__ unsigned g_counter;

// ---------------- helpers ----------------
__device__ __forceinline__ u64 fma2(u64 a, u64 b, u64 c) {
    u64 d; asm("fma.rn.f32x2 %0, %1, %2, %3;" : "=l"(d) : "l"(a), "l"(b), "l"(c)); return d;
}
__device__ __forceinline__ u64 mul2(u64 a, u64 b) {
    u64 d; asm("mul.rn.f32x2 %0, %1, %2;" : "=l"(d) : "l"(a), "l"(b)); return d;
}
__device__ __forceinline__ u64 add2(u64 a, u64 b) {
    u64 d; asm("add.rn.f32x2 %0, %1, %2;" : "=l"(d) : "l"(a), "l"(b)); return d;
}
__device__ __forceinline__ u64 dup2(float x) {
    unsigned xi = __float_as_uint(x);
    u64 d; asm("mov.b64 %0, {%1, %2};" : "=l"(d) : "r"(xi), "r"(xi)); return d;
}
__device__ __forceinline__ void unpack2(u64 v, float& lo, float& hi) {
    unsigned a, b; asm("mov.b64 {%0, %1}, %2;" : "=r"(a), "=r"(b) : "l"(v));
    lo = __uint_as_float(a); hi = __uint_as_float(b);
}
__device__ __forceinline__ unsigned ldacq(const unsigned* p) {
    unsigned v; asm volatile("ld.acquire.gpu.u32 %0, [%1];" : "=r"(v) : "l"(p)); return v;
}
__device__ __forceinline__ unsigned atom_inc_acqrel(unsigned* p) {
    unsigned v, one = 1u;
    asm volatile("atom.add.acq_rel.gpu.u32 %0, [%1], %2;" : "=r"(v) : "l"(p), "r"(one)); return v;
}
__device__ __forceinline__ void redadd(float* p, float v) {
    asm volatile("red.add.f32 [%0], %1;" :: "l"(p), "f"(v));
}

// ---------------- init: matrix inverses + reset ----------------
__global__ void init_kernel(const float* __restrict__ Ap) {
    __shared__ float M[NP][2*NP + 1];
    __shared__ float fac[NP];
    __shared__ float s_piv;
    int t = threadIdx.x;

    for (int pass = 0; pass < 2; ++pass) {
        float dscale = (pass == 0) ? 1.0f : 3.0f;
        float ascale = (pass == 0) ? DTF : 2.0f * DTF;
        for (int idx = t; idx < NP*NP; idx += 256) {
            int i = idx >> 6, j = idx & 63;
            M[i][j]      = ((i == j) ? dscale : 0.0f) - ascale * Ap[idx];
            M[i][j + NP] = (i == j) ? 1.0f : 0.0f;
        }
        __syncthreads();
        for (int c = 0; c < NP; ++c) {
            if (t == 0) s_piv = 1.0f / M[c][c];
            __syncthreads();
            float ip = s_piv;
            if (t < 2*NP) M[c][t] *= ip;
            if (t < NP)   fac[t] = (t == c) ? 0.0f : M[t][c];
            __syncthreads();
            for (int idx = t; idx < NP * 2 * NP; idx += 256) {
                int r = idx >> 7, j = idx & 127;
                if (r != c) M[r][j] -= fac[r] * M[c][j];
            }
            __syncthreads();
        }
        for (int idx = t; idx < NP*NP; idx += 256) {
            int j = idx >> 6, i = idx & 63;
            g_invT[pass][idx] = M[i][j + NP];   // j-major
        }
        __syncthreads();
    }
    for (int idx = t; idx < 4*NB*NP; idx += 256) ((float*)g_S)[idx] = 0.0f;
    if (t == 0) g_counter = 0u;
    __threadfence();
}

// ---------------- SMEM layout (bytes) ----------------
#define SM_W     0                 // [g 55][kslot 64][c 4] f32, k XOR (g&7)  : 56320
#define SM_P     56320             // [g 55][p 64] f32 (stride 256)           : 14080
#define SM_F     70400             // [g 55] stride 144B (16 u64 b-pairs)     : 7920
#define SM_A     78320             // [k 64][bp 16] u64                       : 8192
#define SM_R     86512             // [j 64] stride 136B                      : 8704
#define SM_PART  95216             // 128 slots x 64B partial merge           : 8192
#define SMEM_TOTAL 103408

extern __shared__ char smem_raw[];

__global__ void __launch_bounds__(NT, 2)
persist_kernel(const float* __restrict__ state,
               const float* __restrict__ Wu, const float* __restrict__ Wv,
               const float* __restrict__ Pp, float* __restrict__ out)
{
    const int t   = threadIdx.x;
    const int cta = blockIdx.x;

    const int gstart = (int)(((long)cta * 2000) / 37);
    const int gcnt   = (int)(((long)(cta + 1) * 2000) / 37) - gstart;   // 54 or 55

    // ================= one-time staging =================
    // W: [g][kslot][c], kslot = k ^ (g&7)
    for (int idx = t; idx < gcnt*4*16; idx += NT) {
        int g = idx >> 6, r = (idx >> 4) & 3, k4 = idx & 15;
        int gate = gstart + g;
        const float4* src = (const float4*)((gate < NG) ? Wu : Wv);
        int base = (gate < NG) ? gate : (gate - NG);
        float4 v = __ldg(src + (base + r*NG)*16 + k4);
        float vv[4] = {v.x, v.y, v.z, v.w};
        int xr = g & 7;
        #pragma unroll
        for (int j = 0; j < 4; ++j) {
            int k = k4*4 + j;
            *(float*)(smem_raw + SM_W + g*1024 + (k ^ xr)*16 + r*4) = vv[j];
        }
    }
    // P: [g][p] stride 256B
    for (int idx = t; idx < GPC*NP; idx += NT) {
        int g = idx >> 6, p = idx & 63;
        if (g < gcnt)
            *(float*)(smem_raw + SM_P + g*256 + p*4) = __ldg(Pp + p*NGATE + gstart + g);
    }
    // a: [k][bp] u64
    for (int idx = t; idx < NB*NP; idx += NT) {
        int b = idx >> 6, k = idx & 63;
        *(float*)(smem_raw + SM_A + k*128 + (b >> 1)*8 + (b & 1)*4) = state[idx];
    }

    // ---- static mappings ----
    // phase 1: thread = (gate g1, batch-quarter bq)
    const int g1 = t >> 2, bq = t & 3;
    const bool p1v = (g1 < gcnt);
    const char* wb = smem_raw + SM_W + g1*1024;
    const unsigned xr16 = ((unsigned)(g1 & 7)) * 16u;
    const char* ab = smem_raw + SM_A + bq*32;
    // phase 2: thread = (bq2 4, p8 32, gh 2)
    const int bq2 = t & 3, p8 = (t >> 2) & 31, gh = t >> 7;
    // matvec: thread = (b-pair bpu 16, i-quad i4 16)
    const int bpu = t & 15, i4 = t >> 4;

    float aprv[8], fprv[8];
    #pragma unroll
    for (int e = 0; e < 8; ++e) { aprv[e] = 0.0f; fprv[e] = 0.0f; }

    __syncthreads();

    for (int it = 0; it < NITER; ++it) {
        // ========== phase 1: z = a@W^T (1 gate x 4 comps x 4 bp) ==========
        if (p1v) {
            u64 acc[4][4];
            #pragma unroll
            for (int c = 0; c < 4; ++c)
                #pragma unroll
                for (int i = 0; i < 4; ++i) acc[c][i] = 0;

            #pragma unroll 4
            for (int k = 0; k < NP; ++k) {
                float4 w = *(const float4*)(wb + (((unsigned)(k * 16)) ^ xr16));
                ulonglong2 aA = *(const ulonglong2*)(ab + k*128);
                ulonglong2 aB = *(const ulonglong2*)(ab + k*128 + 16);
                u64 av[4] = {aA.x, aA.y, aB.x, aB.y};
                u64 d[4] = {dup2(w.x), dup2(w.y), dup2(w.z), dup2(w.w)};
                #pragma unroll
                for (int c = 0; c < 4; ++c)
                    #pragma unroll
                    for (int i = 0; i < 4; ++i)
                        acc[c][i] = fma2(d[c], av[i], acc[c][i]);
            }
            // f = u*dx + v*dy
            u64 f0 = fma2(acc[1][0], acc[3][0], mul2(acc[0][0], acc[2][0]));
            u64 f1 = fma2(acc[1][1], acc[3][1], mul2(acc[0][1], acc[2][1]));
            u64 f2 = fma2(acc[1][2], acc[3][2], mul2(acc[0][2], acc[2][2]));
            u64 f3 = fma2(acc[1][3], acc[3][3], mul2(acc[0][3], acc[2][3]));
            char* fb = smem_raw + SM_F + g1*144 + bq*32;
            *(ulonglong2*)(fb)      = make_ulonglong2(f0, f1);
            *(ulonglong2*)(fb + 16) = make_ulonglong2(f2, f3);
        }
        __syncthreads();

        // ========== phase 2: q[2p][4bp] over a gate-split ==========
        u64 q[2][4];
        #pragma unroll
        for (int p = 0; p < 2; ++p)
            #pragma unroll
            for (int i = 0; i < 4; ++i) q[p][i] = 0;
        {
            const char* fb = smem_raw + SM_F + bq2*32;
            const char* pb = smem_raw + SM_P + p8*8;
            const int gg0 = gh ? 28 : 0;
            const int gg1 = gh ? gcnt : 28;
            #pragma unroll 4
            for (int g = gg0; g < gg1; ++g) {
                ulonglong2 fA = *(const ulonglong2*)(fb + g*144);
                ulonglong2 fB = *(const ulonglong2*)(fb + g*144 + 16);
                float2 pv = *(const float2*)(pb + g*256);
                u64 fv[4] = {fA.x, fA.y, fB.x, fB.y};
                u64 pd0 = dup2(pv.x), pd1 = dup2(pv.y);
                #pragma unroll
                for (int i = 0; i < 4; ++i) {
                    q[0][i] = fma2(pd0, fv[i], q[0][i]);
                    q[1][i] = fma2(pd1, fv[i], q[1][i]);
                }
            }
        }
        __syncthreads();
        {
            int slot = bq2*32 + p8;
            char* pa = smem_raw + SM_PART + slot*64;
            if (gh == 1) {
                *(ulonglong2*)(pa)      = make_ulonglong2(q[0][0], q[0][1]);
                *(ulonglong2*)(pa + 16) = make_ulonglong2(q[0][2], q[0][3]);
                *(ulonglong2*)(pa + 32) = make_ulonglong2(q[1][0], q[1][1]);
                *(ulonglong2*)(pa + 48) = make_ulonglong2(q[1][2], q[1][3]);
            }
            __syncthreads();
            if (gh == 0) {
                ulonglong2 v0 = *(const ulonglong2*)(pa);
                ulonglong2 v1 = *(const ulonglong2*)(pa + 16);
                ulonglong2 v2 = *(const ulonglong2*)(pa + 32);
                ulonglong2 v3 = *(const ulonglong2*)(pa + 48);
                q[0][0] = add2(q[0][0], v0.x); q[0][1] = add2(q[0][1], v0.y);
                q[0][2] = add2(q[0][2], v1.x); q[0][3] = add2(q[0][3], v1.y);
                q[1][0] = add2(q[1][0], v2.x); q[1][1] = add2(q[1][1], v2.y);
                q[1][2] = add2(q[1][2], v3.x); q[1][3] = add2(q[1][3], v3.y);
                float* Sb = g_S[it & 3];
                #pragma unroll
                for (int p = 0; p < 2; ++p)
                    #pragma unroll
                    for (int i = 0; i < 4; ++i) {
                        int b = 2*(bq2*4 + i), pp = p8*2 + p;
                        float lo, hi; unpack2(q[p][i], lo, hi);
                        redadd(Sb + b*NP + pp, lo);
                        redadd(Sb + (b + 1)*NP + pp, hi);
                    }
            }
        }

        // ========== single global barrier ==========
        __threadfence();
        __syncthreads();
        if (t == 0) atom_inc_acqrel(&g_counter);
        if (it == NITER - 1 && cta != 0) return;
        if (t == 0) {
            const unsigned tgt = (unsigned)NCTA * (unsigned)(it + 1);
            while (ldacq(&g_counter) < tgt) { }
        }
        __syncthreads();

        // zero buffer used 1 iter ago (rewritten at it+3; ordered by barrier chain)
        if (t < 7) {
            int z = cta*7 + t;
            if (z < NB*NP) __stcg(&g_S[(it + 3) & 3][z], 0.0f);
        }

        // ========== update step 1: r ==========
        {
            const float* Sb = g_S[it & 3];
            #pragma unroll
            for (int e = 0; e < 8; ++e) {
                int idx = t + e*NT;
                int b = idx >> 6, j = idx & 63;
                float f  = -__ldcv(Sb + idx);
                float av = *(const float*)(smem_raw + SM_A + j*128 + (b >> 1)*8 + (b & 1)*4);
                float r;
                if (it == 0) r = av + DTF * f;
                else         r = 4.0f*av - aprv[e] + 4.0f*DTF*f - 2.0f*DTF*fprv[e];
                aprv[e] = av; fprv[e] = f;
                *(float*)(smem_raw + SM_R + j*136 + (b >> 1)*8 + (b & 1)*4) = r;
            }
        }
        __syncthreads();

        // ========== update step 2: a_next = inv @ r (inv via L1) ==========
        {
            const float* invg = g_invT[(it == 0) ? 0 : 1];
            u64 m[4] = {0, 0, 0, 0};
            const char* rb = smem_raw + SM_R + bpu*8;
            #pragma unroll 4
            for (int j = 0; j < NP; ++j) {
                u64 rv = *(const u64*)(rb + j*136);
                float4 iv = __ldg((const float4*)(invg + j*64 + i4*4));
                m[0] = fma2(rv, dup2(iv.x), m[0]);
                m[1] = fma2(rv, dup2(iv.y), m[1]);
                m[2] = fma2(rv, dup2(iv.z), m[2]);
                m[3] = fma2(rv, dup2(iv.w), m[3]);
            }
            if (it < NITER - 1) {
                #pragma unroll
                for (int qq = 0; qq < 4; ++qq)
                    *(u64*)(smem_raw + SM_A + (i4*4 + qq)*128 + bpu*8) = m[qq];
            } else {   // only CTA0 reaches here
                #pragma unroll
                for (int qq = 0; qq < 4; ++qq) {
                    int i = i4*4 + qq;
                    float lo, hi; unpack2(m[qq], lo, hi);
                    out[(2*bpu    )*NP + i] = (lo - __ldg(&state[(2*bpu    )*NP + i])) * INV_DT_SKIP;
                    out[(2*bpu + 1)*NP + i] = (hi - __ldg(&state[(2*bpu + 1)*NP + i])) * INV_DT_SKIP;
                }
            }
        }
        __syncthreads();
    }
}

// ---------------- launcher ----------------
extern "C" void kernel_launch(void* const* d_in, const int* in_sizes, int n_in,
                              void* d_out, int out_size) {
    const float* state = (const float*)d_in[0];
    const float* Ap    = (const float*)d_in[1];
    const float* Wu    = (const float*)d_in[2];
    const float* Wv    = (const float*)d_in[3];
    const float* Pp    = (const float*)d_in[4];
    float* out = (float*)d_out;
    (void)in_sizes; (void)n_in; (void)out_size;

    cudaFuncSetAttribute(persist_kernel,
                         cudaFuncAttributeMaxDynamicSharedMemorySize, SMEM_TOTAL);

    init_kernel<<<1, 256>>>(Ap);
    persist_kernel<<<NCTA, NT, SMEM_TOTAL>>>(state, Wu, Wv, Pp, out);
}